// round 11
// baseline (speedup 1.0000x reference)
#include <cuda_runtime.h>
#include <cuda_bf16.h>

#define THREADS 256
#define ITER 4
#define ROWS_PER_BLOCK (THREADS * ITER)
#define GMAX 4096

// {count, sum_col11, sum_col24, pad} per graph; zero-initialized at module load.
// mlp_reset_kernel re-zeroes after consuming, so every replay starts from zeros.
__device__ float4 g_acc[GMAX];

// Segmented sum over sorted batch ids. ITER nodes per thread, front-batched
// loads for ILP. Warp-segmented reduction: only contiguous-run leaders atomic.
__global__ void __launch_bounds__(THREADS)
seg_reduce_kernel(const float* __restrict__ nf,
                  const int* __restrict__ batch,
                  int N) {
    const int lane = threadIdx.x & 31;
    const int base = blockIdx.x * ROWS_PER_BLOCK;

    // Batch ids first (needed earliest, fully coalesced).
    int g[ITER];
    #pragma unroll
    for (int it = 0; it < ITER; it++) {
        int i = base + it * THREADS + threadIdx.x;
        g[it] = (i < N) ? __ldcs(batch + i) : -1;
    }

    // Feature loads: 2 per row, streaming (no reuse).
    float v0[ITER], v1[ITER];
    #pragma unroll
    for (int it = 0; it < ITER; it++) {
        int i = base + it * THREADS + threadIdx.x;
        if (i < N) {
            const float* row = nf + (size_t)i * 128;
            v0[it] = __ldcs(row + 11);   // MODIFIER_COL
            v1[it] = __ldcs(row + 24);   // OWNER_COL
        } else { v0[it] = 0.0f; v1[it] = 0.0f; }
    }

    #pragma unroll
    for (int it = 0; it < ITER; it++) {
        unsigned peers  = __match_any_sync(0xffffffffu, g[it]);
        int      leader = __ffs(peers) - 1;
        int      cnt    = __popc(peers);
        float a0 = v0[it], a1 = v1[it];
        #pragma unroll
        for (int off = 16; off > 0; off >>= 1) {
            float t0 = __shfl_down_sync(0xffffffffu, a0, off);
            float t1 = __shfl_down_sync(0xffffffffu, a1, off);
            if (lane + off < leader + cnt) { a0 += t0; a1 += t1; }
        }
        if (lane == leader && g[it] >= 0) {
            float* bp = (float*)&g_acc[g[it]];
            atomicAdd(bp + 0, (float)cnt);
            atomicAdd(bp + 1, a0);
            atomicAdd(bp + 2, a1);
        }
    }
}

// Consume accumulators, run tiny MLP, write out, RESET accumulators for the
// next replay. PDL: launches during seg_reduce; weights load before the
// dependency sync so only the g_acc read chain is exposed.
__global__ void mlp_reset_kernel(const float* __restrict__ W1,   // [32,2]
                                 const float* __restrict__ b1,   // [32]
                                 const float* __restrict__ W2,   // [1,32]
                                 const float* __restrict__ b2,   // [1]
                                 float* __restrict__ out, int G) {
    int g = blockIdx.x * blockDim.x + threadIdx.x;

    // Independent prologue: pull weights while the primary kernel drains.
    float w1a[32], w1b[32], w2[32];
    float bb1[32], bias2 = __ldg(b2);
    #pragma unroll
    for (int j = 0; j < 32; j++) {
        w1a[j] = __ldg(W1 + j * 2 + 0);
        w1b[j] = __ldg(W1 + j * 2 + 1);
        bb1[j] = __ldg(b1 + j);
        w2[j]  = __ldg(W2 + j);
    }

#if __CUDA_ARCH__ >= 900
    cudaGridDependencySynchronize();
#endif

    if (g >= G) return;

    float4 a = g_acc[g];                         // one LDG.128
    g_acc[g] = make_float4(0.f, 0.f, 0.f, 0.f);  // one STG.128 reset

    float denom = fmaxf(a.x, 1.0f);
    float a0 = 1.0f - a.y / denom;
    float a1 = 1.0f - a.z / denom;

    float acc = bias2;
    #pragma unroll
    for (int j = 0; j < 32; j++) {
        float h = fmaf(a0, w1a[j], fmaf(a1, w1b[j], bb1[j]));
        h = fmaxf(h, 0.0f);
        acc = fmaf(h, w2[j], acc);
    }
    float score = 1.0f / (1.0f + __expf(-acc));
    out[g] = (a.x > 0.0f) ? score : 0.0f;
}

extern "C" void kernel_launch(void* const* d_in, const int* in_sizes, int n_in,
                              void* d_out, int out_size) {
    // metadata order: node_features, batch, graph_embedding(unused), W1, b1, W2, b2
    const float* nf    = (const float*)d_in[0];
    const int*   batch = (const int*)d_in[1];
    const float* W1    = (const float*)d_in[3];
    const float* b1    = (const float*)d_in[4];
    const float* W2    = (const float*)d_in[5];
    const float* b2    = (const float*)d_in[6];
    float*       out   = (float*)d_out;

    int N = in_sizes[1];   // number of nodes
    int G = out_size;      // number of graphs
    if (G > GMAX) G = GMAX;

    int nblocks = (N + ROWS_PER_BLOCK - 1) / ROWS_PER_BLOCK;
    seg_reduce_kernel<<<nblocks, THREADS>>>(nf, batch, N);

    // PDL launch of the epilogue: overlaps its launch + weight loads with seg_reduce.
    cudaLaunchConfig_t cfg = {};
    cfg.gridDim  = dim3((G + THREADS - 1) / THREADS);
    cfg.blockDim = dim3(THREADS);
    cudaLaunchAttribute attr[1];
    attr[0].id = cudaLaunchAttributeProgrammaticStreamSerialization;
    attr[0].val.programmaticStreamSerializationAllowed = 1;
    cfg.attrs = attr;
    cfg.numAttrs = 1;
    cudaLaunchKernelEx(&cfg, mlp_reset_kernel, W1, b1, W2, b2, out, G);
}

// round 12
// speedup vs baseline: 1.0918x; 1.0918x over previous
#include <cuda_runtime.h>
#include <cuda_bf16.h>

#define THREADS 256
#define ITER 2
#define ROWS_PER_BLOCK (THREADS * ITER)
#define GMAX 4096

// {count, sum_col11, sum_col24, pad} per graph; zero-initialized at module load.
// mlp_reset_kernel re-zeroes after consuming, so every replay starts from zeros.
__device__ float4 g_acc[GMAX];

// Segmented sum over sorted batch ids. ITER nodes per thread, front-batched
// loads for ILP. Warp-segmented reduction: only contiguous-run leaders atomic.
// Triggers programmatic launch completion after its atomics so the PDL
// consumer can start before grid teardown.
__global__ void __launch_bounds__(THREADS)
seg_reduce_kernel(const float* __restrict__ nf,
                  const int* __restrict__ batch,
                  int N) {
    const int lane = threadIdx.x & 31;
    const int base = blockIdx.x * ROWS_PER_BLOCK;

    int   g[ITER];
    float v0[ITER], v1[ITER];
    #pragma unroll
    for (int it = 0; it < ITER; it++) {
        int i = base + it * THREADS + threadIdx.x;
        if (i < N) {
            g[it] = __ldcs(batch + i);
            const float* row = nf + (size_t)i * 128;
            v0[it] = __ldcs(row + 11);   // MODIFIER_COL (streaming, no reuse)
            v1[it] = __ldcs(row + 24);   // OWNER_COL
        } else {
            g[it] = -1; v0[it] = 0.0f; v1[it] = 0.0f;
        }
    }

    #pragma unroll
    for (int it = 0; it < ITER; it++) {
        unsigned peers  = __match_any_sync(0xffffffffu, g[it]);
        int      leader = __ffs(peers) - 1;
        int      cnt    = __popc(peers);
        float a0 = v0[it], a1 = v1[it];
        #pragma unroll
        for (int off = 16; off > 0; off >>= 1) {
            float t0 = __shfl_down_sync(0xffffffffu, a0, off);
            float t1 = __shfl_down_sync(0xffffffffu, a1, off);
            if (lane + off < leader + cnt) { a0 += t0; a1 += t1; }
        }
        if (lane == leader && g[it] >= 0) {
            float* bp = (float*)&g_acc[g[it]];
            atomicAdd(bp + 0, (float)cnt);
            atomicAdd(bp + 1, a0);
            atomicAdd(bp + 2, a1);
        }
    }

#if __CUDA_ARCH__ >= 900
    // All block atomics issued; release them to the dependent grid now so
    // mlp_reset can run during this grid's drain/teardown.
    __syncthreads();
    cudaTriggerProgrammaticLaunchCompletion();
#endif
}

// Consume accumulators, run tiny MLP, write out, RESET accumulators for the
// next replay. PDL: launches during seg_reduce; weights load before the
// dependency sync so only the g_acc read chain is exposed.
__global__ void mlp_reset_kernel(const float* __restrict__ W1,   // [32,2]
                                 const float* __restrict__ b1,   // [32]
                                 const float* __restrict__ W2,   // [1,32]
                                 const float* __restrict__ b2,   // [1]
                                 float* __restrict__ out, int G) {
    int g = blockIdx.x * blockDim.x + threadIdx.x;

    // Independent prologue: pull weights while the primary kernel drains.
    float w1a[32], w1b[32], w2[32];
    float bb1[32], bias2 = __ldg(b2);
    #pragma unroll
    for (int j = 0; j < 32; j++) {
        w1a[j] = __ldg(W1 + j * 2 + 0);
        w1b[j] = __ldg(W1 + j * 2 + 1);
        bb1[j] = __ldg(b1 + j);
        w2[j]  = __ldg(W2 + j);
    }

#if __CUDA_ARCH__ >= 900
    cudaGridDependencySynchronize();
#endif

    if (g >= G) return;

    float4 a = g_acc[g];                         // one LDG.128
    g_acc[g] = make_float4(0.f, 0.f, 0.f, 0.f);  // one STG.128 reset

    float denom = fmaxf(a.x, 1.0f);
    float a0 = 1.0f - a.y / denom;
    float a1 = 1.0f - a.z / denom;

    float acc = bias2;
    #pragma unroll
    for (int j = 0; j < 32; j++) {
        float h = fmaf(a0, w1a[j], fmaf(a1, w1b[j], bb1[j]));
        h = fmaxf(h, 0.0f);
        acc = fmaf(h, w2[j], acc);
    }
    float score = 1.0f / (1.0f + __expf(-acc));
    out[g] = (a.x > 0.0f) ? score : 0.0f;
}

extern "C" void kernel_launch(void* const* d_in, const int* in_sizes, int n_in,
                              void* d_out, int out_size) {
    // metadata order: node_features, batch, graph_embedding(unused), W1, b1, W2, b2
    const float* nf    = (const float*)d_in[0];
    const int*   batch = (const int*)d_in[1];
    const float* W1    = (const float*)d_in[3];
    const float* b1    = (const float*)d_in[4];
    const float* W2    = (const float*)d_in[5];
    const float* b2    = (const float*)d_in[6];
    float*       out   = (float*)d_out;

    int N = in_sizes[1];   // number of nodes
    int G = out_size;      // number of graphs
    if (G > GMAX) G = GMAX;

    int nblocks = (N + ROWS_PER_BLOCK - 1) / ROWS_PER_BLOCK;
    seg_reduce_kernel<<<nblocks, THREADS>>>(nf, batch, N);

    // PDL launch of the epilogue: overlaps its launch + weight loads with seg_reduce.
    cudaLaunchConfig_t cfg = {};
    cfg.gridDim  = dim3((G + THREADS - 1) / THREADS);
    cfg.blockDim = dim3(THREADS);
    cudaLaunchAttribute attr[1];
    attr[0].id = cudaLaunchAttributeProgrammaticStreamSerialization;
    attr[0].val.programmaticStreamSerializationAllowed = 1;
    cfg.attrs = attr;
    cfg.numAttrs = 1;
    cudaLaunchKernelEx(&cfg, mlp_reset_kernel, W1, b1, W2, b2, out, G);
}